// round 6
// baseline (speedup 1.0000x reference)
#include <cuda_runtime.h>
#include <cuda_bf16.h>
#include <math.h>
#include <stdint.h>

#define B_  2
#define N_  2048
#define C_  1024
#define H_  16
#define DH  64

// Scratch (device globals: allocation-free per harness rules)
__device__ float g_q[B_*H_*N_*DH];
__device__ float g_k[B_*H_*N_*DH];
__device__ float g_v[B_*H_*N_*DH];
__device__ float g_att[B_*N_*C_];

__device__ __forceinline__ uint32_t f2tf(float f) {
    uint32_t u;
    asm("cvt.rna.tf32.f32 %0, %1;" : "=r"(u) : "f"(f));
    return u;
}

__device__ __forceinline__ void mma_tf32(float c[4], uint32_t a0, uint32_t a1,
                                         uint32_t a2, uint32_t a3,
                                         uint32_t b0, uint32_t b1) {
    asm volatile(
        "mma.sync.aligned.m16n8k8.row.col.f32.tf32.tf32.f32 "
        "{%0,%1,%2,%3}, {%4,%5,%6,%7}, {%8,%9}, {%0,%1,%2,%3};"
        : "+f"(c[0]), "+f"(c[1]), "+f"(c[2]), "+f"(c[3])
        : "r"(a0), "r"(a1), "r"(a2), "r"(a3), "r"(b0), "r"(b1));
}

__device__ __forceinline__ void cp16(uint32_t smem_addr, const void* gptr) {
    asm volatile("cp.async.cg.shared.global [%0], [%1], 16;"
                 :: "r"(smem_addr), "l"(__cvta_generic_to_global(gptr)));
}
__device__ __forceinline__ void cp_commit() {
    asm volatile("cp.async.commit_group;");
}
__device__ __forceinline__ void cp_wait1() {
    asm volatile("cp.async.wait_group 1;");
}
__device__ __forceinline__ void cp_wait0() {
    asm volatile("cp.async.wait_group 0;");
}

// ---------------------------------------------------------------------------
// Generic tf32 GEMM body: out = A[m][k] * W[j][k], CTA tile 128x128x32,
// 2-stage cp.async pipeline (race-free: trailing barrier after compute).
// Staging raw fp32, cvt at fragment load.
// ---------------------------------------------------------------------------
#define GEMM_STAGE_WORDS 9216          // (128*36)*2 arrays
#define GEMM_SMEM_BYTES  (2 * GEMM_STAGE_WORDS * 4)   // 73728

__device__ __forceinline__ void gemm_pipeline_128(
    const float* __restrict__ Asrc, const float* __restrict__ Bsrc,
    int m0, int j0, float c[4][4][4], uint32_t* sm)
{
    const int tid = threadIdx.x;
    const int lane = tid & 31;
    const int wid = tid >> 5;
    const int wm = wid >> 2;
    const int wn = wid & 3;
    const int g = lane >> 2;
    const int t = lane & 3;

    const int sr = tid >> 1;        // 0..127
    const int sc = (tid & 1) * 16;  // 0 or 16

    const uint32_t smem_base = (uint32_t)__cvta_generic_to_shared(sm);

    #pragma unroll
    for (int mf = 0; mf < 4; mf++)
        #pragma unroll
        for (int nf = 0; nf < 4; nf++)
            #pragma unroll
            for (int i = 0; i < 4; i++) c[mf][nf][i] = 0.f;

    // prologue: stage 0
    {
        const float* sA = &Asrc[(size_t)(m0 + sr) * C_ + sc];
        const float* sB = &Bsrc[(size_t)(j0 + sr) * C_ + sc];
        const uint32_t dA = smem_base + (sr * 36 + sc) * 4;
        const uint32_t dB = smem_base + (4608 + sr * 36 + sc) * 4;
        #pragma unroll
        for (int i = 0; i < 4; i++) {
            cp16(dA + i * 16, sA + i * 4);
            cp16(dB + i * 16, sB + i * 4);
        }
        cp_commit();
    }

    for (int it = 0; it < C_ / 32; it++) {
        if (it + 1 < C_ / 32) {
            const int k0 = (it + 1) * 32;
            const uint32_t stg = ((it + 1) & 1) * GEMM_STAGE_WORDS;
            const float* sA = &Asrc[(size_t)(m0 + sr) * C_ + k0 + sc];
            const float* sB = &Bsrc[(size_t)(j0 + sr) * C_ + k0 + sc];
            const uint32_t dA = smem_base + (stg + sr * 36 + sc) * 4;
            const uint32_t dB = smem_base + (stg + 4608 + sr * 36 + sc) * 4;
            #pragma unroll
            for (int i = 0; i < 4; i++) {
                cp16(dA + i * 16, sA + i * 4);
                cp16(dB + i * 16, sB + i * 4);
            }
            cp_commit();
            cp_wait1();
        } else {
            cp_wait0();
        }
        __syncthreads();

        const uint32_t* As = sm + (it & 1) * GEMM_STAGE_WORDS;
        const uint32_t* Ws = As + 4608;

        #pragma unroll
        for (int kk = 0; kk < 4; kk++) {
            const int k8 = kk * 8;
            uint32_t a[4][4];
            #pragma unroll
            for (int mf = 0; mf < 4; mf++) {
                const int r0 = wm * 64 + mf * 16 + g;
                a[mf][0] = f2tf(__uint_as_float(As[r0 * 36 + k8 + t]));
                a[mf][1] = f2tf(__uint_as_float(As[(r0 + 8) * 36 + k8 + t]));
                a[mf][2] = f2tf(__uint_as_float(As[r0 * 36 + k8 + t + 4]));
                a[mf][3] = f2tf(__uint_as_float(As[(r0 + 8) * 36 + k8 + t + 4]));
            }
            #pragma unroll
            for (int nf = 0; nf < 4; nf++) {
                const int jr = wn * 32 + nf * 8 + g;
                uint32_t b0 = f2tf(__uint_as_float(Ws[jr * 36 + k8 + t]));
                uint32_t b1 = f2tf(__uint_as_float(Ws[jr * 36 + k8 + t + 4]));
                #pragma unroll
                for (int mf = 0; mf < 4; mf++)
                    mma_tf32(c[mf][nf], a[mf][0], a[mf][1], a[mf][2], a[mf][3], b0, b1);
            }
        }
        // RACE FIX: all threads must finish consuming this stage's buffer
        // before anyone issues the next iteration's cp.async into it.
        __syncthreads();
    }
}

// ---------------------------------------------------------------------------
// QKV GEMM: M=4096, N=3072, K=1024; scatter epilogue to g_q/g_k/g_v
// ---------------------------------------------------------------------------
__global__ __launch_bounds__(256, 2) void qkv_gemm_kernel(
    const float* __restrict__ x, const float* __restrict__ w)
{
    extern __shared__ uint32_t sm[];
    const int tid = threadIdx.x;
    const int lane = tid & 31;
    const int wid = tid >> 5;
    const int wm = wid >> 2;
    const int wn = wid & 3;
    const int g = lane >> 2;
    const int t = lane & 3;
    const int m0 = blockIdx.y * 128;
    const int j0 = blockIdx.x * 128;

    float c[4][4][4];
    gemm_pipeline_128(x, w, m0, j0, c, sm);

    #pragma unroll
    for (int nf = 0; nf < 4; nf++) {
        const int j = j0 + wn * 32 + nf * 8 + 2 * t;
        const int which = j >> 10;
        const int h = (j >> 6) & (H_ - 1);
        const int d = j & (DH - 1);
        float* dst = (which == 0) ? g_q : (which == 1) ? g_k : g_v;
        #pragma unroll
        for (int mf = 0; mf < 4; mf++) {
            const int m = m0 + wm * 64 + mf * 16 + g;
            const int b = m >> 11;
            const int n = m & (N_ - 1);
            *reinterpret_cast<float2*>(&dst[(((size_t)b * H_ + h) * N_ + n) * DH + d]) =
                make_float2(c[mf][nf][0], c[mf][nf][1]);
            const int m2 = m + 8;
            const int b2 = m2 >> 11;
            const int n2 = m2 & (N_ - 1);
            *reinterpret_cast<float2*>(&dst[(((size_t)b2 * H_ + h) * N_ + n2) * DH + d]) =
                make_float2(c[mf][nf][2], c[mf][nf][3]);
        }
    }
}

// ---------------------------------------------------------------------------
// Output projection: M=4096, N=1024, K=1024, bias epilogue
// ---------------------------------------------------------------------------
__global__ __launch_bounds__(256, 2) void proj_gemm_kernel(
    const float* __restrict__ w, const float* __restrict__ bias,
    float* __restrict__ out)
{
    extern __shared__ uint32_t sm[];
    const int tid = threadIdx.x;
    const int lane = tid & 31;
    const int wid = tid >> 5;
    const int wm = wid >> 2;
    const int wn = wid & 3;
    const int g = lane >> 2;
    const int t = lane & 3;
    const int m0 = blockIdx.y * 128;
    const int j0 = blockIdx.x * 128;

    float c[4][4][4];
    gemm_pipeline_128(g_att, w, m0, j0, c, sm);

    #pragma unroll
    for (int nf = 0; nf < 4; nf++) {
        const int j = j0 + wn * 32 + nf * 8 + 2 * t;
        const float b0v = bias[j];
        const float b1v = bias[j + 1];
        #pragma unroll
        for (int mf = 0; mf < 4; mf++) {
            const int m = m0 + wm * 64 + mf * 16 + g;
            *reinterpret_cast<float2*>(&out[(size_t)m * C_ + j]) =
                make_float2(c[mf][nf][0] + b0v, c[mf][nf][1] + b1v);
            *reinterpret_cast<float2*>(&out[(size_t)(m + 8) * C_ + j]) =
                make_float2(c[mf][nf][2] + b0v, c[mf][nf][3] + b1v);
        }
    }
}

// ---------------------------------------------------------------------------
// RoPE 2D applied in-place to g_q and g_k.
// ---------------------------------------------------------------------------
__global__ __launch_bounds__(256) void rope_kernel(const int* __restrict__ pos)
{
    const int tt = blockIdx.x * blockDim.x + threadIdx.x;
    const int total = B_ * H_ * N_ * 32;
    if (tt >= total) return;

    const int p = tt & 31;
    const int row = tt >> 5;          // (b*H + h)*N + n
    const int n = row & (N_ - 1);
    const int bh = row >> 11;
    const int b = bh >> 4;

    const int halfsel = p >> 4;
    const int i = p & 15;
    const int d1 = halfsel * 32 + i;
    const int d2 = d1 + 16;

    const float posv = (float)pos[((size_t)b * N_ + n) * 2 + halfsel];
    const float inv_freq = powf(100.0f, -(float)i / 16.0f);
    const float ang = posv * inv_freq;
    const float s = sinf(ang);
    const float c = cosf(ang);

    const size_t base = (size_t)row * DH;
    float q1 = g_q[base + d1], q2 = g_q[base + d2];
    g_q[base + d1] = q1 * c - q2 * s;
    g_q[base + d2] = q1 * s + q2 * c;
    float k1 = g_k[base + d1], k2 = g_k[base + d2];
    g_k[base + d1] = k1 * c - k2 * s;
    g_k[base + d2] = k1 * s + k2 * c;
}

// ---------------------------------------------------------------------------
// Flash attention (tf32 mma): CTA = (b, h, 128-query rows), 256 thr = 8 warps.
// Warp w owns query rows w*16..w*16+15. Key tile 64, cp.async double-buffered
// (race-free: trailing barrier after PV). P fragments remapped S->A via quad
// shuffles (no smem round trip).
// Smem words: Qs[128*68] | K0[64*68] | K1[64*68] | V0[64*72] | V1[64*72]
// ---------------------------------------------------------------------------
#define AQ_W   (128*68)
#define AK_W   (64*68)
#define AV_W   (64*72)
#define ATTN_SMEM_BYTES ((AQ_W + 2*AK_W + 2*AV_W) * 4)   // 106496

__global__ __launch_bounds__(256, 2) void attn_kernel()
{
    extern __shared__ uint32_t smw[];
    uint32_t* Qs = smw;
    uint32_t* Kb[2] = { smw + AQ_W, smw + AQ_W + AK_W };
    uint32_t* Vb[2] = { smw + AQ_W + 2 * AK_W, smw + AQ_W + 2 * AK_W + AV_W };

    const int tid = threadIdx.x;
    const int lane = tid & 31;
    const int wid = tid >> 5;
    const int g = lane >> 2;
    const int t = lane & 3;
    const int rb = wid * 16;

    const int q0 = blockIdx.x * 128;
    const int h = blockIdx.y;
    const int b = blockIdx.z;

    const float* qptr = g_q + ((size_t)b * H_ + h) * N_ * DH;
    const float* kptr = g_k + ((size_t)b * H_ + h) * N_ * DH;
    const float* vptr = g_v + ((size_t)b * H_ + h) * N_ * DH;

    const uint32_t smem_base = (uint32_t)__cvta_generic_to_shared(smw);
    const uint32_t qs_a = smem_base;
    const uint32_t kb_a[2] = { smem_base + AQ_W * 4, smem_base + (AQ_W + AK_W) * 4 };
    const uint32_t vb_a[2] = { smem_base + (AQ_W + 2 * AK_W) * 4,
                               smem_base + (AQ_W + 2 * AK_W + AV_W) * 4 };

    // prologue: stage Q (8 chunks) + K/V tile 0 (4+4 chunks), one group
    #pragma unroll
    for (int ii = 0; ii < 8; ii++) {
        const int idx = tid + ii * 256;
        const int r = idx >> 4;
        const int c4 = (idx & 15) * 4;
        cp16(qs_a + (r * 68 + c4) * 4, qptr + (size_t)(q0 + r) * DH + c4);
    }
    #pragma unroll
    for (int ii = 0; ii < 4; ii++) {
        const int idx = tid + ii * 256;
        const int r = idx >> 4;
        const int c4 = (idx & 15) * 4;
        cp16(kb_a[0] + (r * 68 + c4) * 4, kptr + (size_t)r * DH + c4);
        cp16(vb_a[0] + (r * 72 + c4) * 4, vptr + (size_t)r * DH + c4);
    }
    cp_commit();

    float o[8][4];
    #pragma unroll
    for (int df = 0; df < 8; df++)
        #pragma unroll
        for (int i = 0; i < 4; i++) o[df][i] = 0.f;
    float mrow0 = -1e30f, mrow1 = -1e30f, lrow0 = 0.f, lrow1 = 0.f;

    for (int kt = 0; kt < N_ / 64; kt++) {
        if (kt + 1 < N_ / 64) {
            const int n1 = (kt + 1) * 64;
            const int bsel = (kt + 1) & 1;
            #pragma unroll
            for (int ii = 0; ii < 4; ii++) {
                const int idx = tid + ii * 256;
                const int r = idx >> 4;
                const int c4 = (idx & 15) * 4;
                cp16(kb_a[bsel] + (r * 68 + c4) * 4, kptr + (size_t)(n1 + r) * DH + c4);
                cp16(vb_a[bsel] + (r * 72 + c4) * 4, vptr + (size_t)(n1 + r) * DH + c4);
            }
            cp_commit();
            cp_wait1();
        } else {
            cp_wait0();
        }
        __syncthreads();

        if (kt == 0) {
            // in-place cvt of Q with softmax scale folded
            #pragma unroll
            for (int ii = 0; ii < 8; ii++) {
                const int idx = tid + ii * 256;
                const int r = idx >> 4;
                const int c4 = (idx & 15) * 4;
                uint4 u = *reinterpret_cast<uint4*>(&Qs[r * 68 + c4]);
                u.x = f2tf(__uint_as_float(u.x) * 0.125f);
                u.y = f2tf(__uint_as_float(u.y) * 0.125f);
                u.z = f2tf(__uint_as_float(u.z) * 0.125f);
                u.w = f2tf(__uint_as_float(u.w) * 0.125f);
                *reinterpret_cast<uint4*>(&Qs[r * 68 + c4]) = u;
            }
            __syncthreads();
        }

        const uint32_t* Ks = Kb[kt & 1];
        const uint32_t* Vs = Vb[kt & 1];

        // S = Q K^T for this warp's 16 rows x 64 keys
        float s[8][4];
        #pragma unroll
        for (int nf = 0; nf < 8; nf++)
            #pragma unroll
            for (int i = 0; i < 4; i++) s[nf][i] = 0.f;

        #pragma unroll
        for (int k8 = 0; k8 < 64; k8 += 8) {
            uint32_t a0 = Qs[(rb + g) * 68 + k8 + t];
            uint32_t a1 = Qs[(rb + g + 8) * 68 + k8 + t];
            uint32_t a2 = Qs[(rb + g) * 68 + k8 + t + 4];
            uint32_t a3 = Qs[(rb + g + 8) * 68 + k8 + t + 4];
            #pragma unroll
            for (int nf = 0; nf < 8; nf++) {
                uint32_t b0 = f2tf(__uint_as_float(Ks[(nf * 8 + g) * 68 + k8 + t]));
                uint32_t b1 = f2tf(__uint_as_float(Ks[(nf * 8 + g) * 68 + k8 + t + 4]));
                mma_tf32(s[nf], a0, a1, a2, a3, b0, b1);
            }
        }

        // Online softmax. Row g -> (c0,c1), row g+8 -> (c2,c3).
        float rmax0 = -1e30f, rmax1 = -1e30f;
        #pragma unroll
        for (int nf = 0; nf < 8; nf++) {
            rmax0 = fmaxf(rmax0, fmaxf(s[nf][0], s[nf][1]));
            rmax1 = fmaxf(rmax1, fmaxf(s[nf][2], s[nf][3]));
        }
        #pragma unroll
        for (int off = 1; off < 4; off <<= 1) {
            rmax0 = fmaxf(rmax0, __shfl_xor_sync(0xffffffffu, rmax0, off));
            rmax1 = fmaxf(rmax1, __shfl_xor_sync(0xffffffffu, rmax1, off));
        }
        const float newm0 = fmaxf(mrow0, rmax0);
        const float newm1 = fmaxf(mrow1, rmax1);
        const float corr0 = __expf(mrow0 - newm0);
        const float corr1 = __expf(mrow1 - newm1);

        float rsum0 = 0.f, rsum1 = 0.f;
        #pragma unroll
        for (int nf = 0; nf < 8; nf++) {
            float p0 = __expf(s[nf][0] - newm0);
            float p1 = __expf(s[nf][1] - newm0);
            float p2 = __expf(s[nf][2] - newm1);
            float p3 = __expf(s[nf][3] - newm1);
            rsum0 += p0 + p1;
            rsum1 += p2 + p3;
            // store tf32 bits back into s for the shuffle-based A-frag remap
            s[nf][0] = __uint_as_float(f2tf(p0));
            s[nf][1] = __uint_as_float(f2tf(p1));
            s[nf][2] = __uint_as_float(f2tf(p2));
            s[nf][3] = __uint_as_float(f2tf(p3));
        }
        #pragma unroll
        for (int off = 1; off < 4; off <<= 1) {
            rsum0 += __shfl_xor_sync(0xffffffffu, rsum0, off);
            rsum1 += __shfl_xor_sync(0xffffffffu, rsum1, off);
        }
        lrow0 = lrow0 * corr0 + rsum0;
        lrow1 = lrow1 * corr1 + rsum1;
        mrow0 = newm0;
        mrow1 = newm1;
        #pragma unroll
        for (int df = 0; df < 8; df++) {
            o[df][0] *= corr0; o[df][1] *= corr0;
            o[df][2] *= corr1; o[df][3] *= corr1;
        }

        // O += P V. A-frags built from S-frags via quad shuffles:
        // A(g, t) of k8-chunk kk lives in S-lane (g, t>>1), reg (t&1).
        const int srcA = (g << 2) + (t >> 1);
        const int srcB = srcA + 2;
        #pragma unroll
        for (int kk = 0; kk < 8; kk++) {
            float v00 = __shfl_sync(0xffffffffu, s[kk][0], srcA);
            float v01 = __shfl_sync(0xffffffffu, s[kk][1], srcA);
            float v10 = __shfl_sync(0xffffffffu, s[kk][2], srcA);
            float v11 = __shfl_sync(0xffffffffu, s[kk][3], srcA);
            float w00 = __shfl_sync(0xffffffffu, s[kk][0], srcB);
            float w01 = __shfl_sync(0xffffffffu, s[kk][1], srcB);
            float w10 = __shfl_sync(0xffffffffu, s[kk][2], srcB);
            float w11 = __shfl_sync(0xffffffffu, s[kk][3], srcB);
            uint32_t a0 = __float_as_uint((t & 1) ? v01 : v00);
            uint32_t a1 = __float_as_uint((t & 1) ? v11 : v10);
            uint32_t a2 = __float_as_uint((t & 1) ? w01 : w00);
            uint32_t a3 = __float_as_uint((t & 1) ? w11 : w10);
            const int k8 = kk * 8;
            #pragma unroll
            for (int df = 0; df < 8; df++) {
                uint32_t b0 = f2tf(__uint_as_float(Vs[(k8 + t) * 72 + df * 8 + g]));
                uint32_t b1 = f2tf(__uint_as_float(Vs[(k8 + t + 4) * 72 + df * 8 + g]));
                mma_tf32(o[df], a0, a1, a2, a3, b0, b1);
            }
        }
        // RACE FIX: everyone done reading K/V buffers for this tile before the
        // next iteration's cp.async may overwrite the other (previous) buffer.
        __syncthreads();
    }

    // Normalize + store to g_att [B, N, H*DH]
    const float inv0 = 1.0f / lrow0;
    const float inv1 = 1.0f / lrow1;
    const int n0 = q0 + rb + g;
    const int n1 = n0 + 8;
    #pragma unroll
    for (int df = 0; df < 8; df++) {
        const int d = df * 8 + 2 * t;
        *reinterpret_cast<float2*>(&g_att[((size_t)b * N_ + n0) * C_ + h * DH + d]) =
            make_float2(o[df][0] * inv0, o[df][1] * inv0);
        *reinterpret_cast<float2*>(&g_att[((size_t)b * N_ + n1) * C_ + h * DH + d]) =
            make_float2(o[df][2] * inv1, o[df][3] * inv1);
    }
}

// ---------------------------------------------------------------------------
extern "C" void kernel_launch(void* const* d_in, const int* in_sizes, int n_in,
                              void* d_out, int out_size)
{
    const float* x      = (const float*)d_in[0];
    const int*   pos    = (const int*)  d_in[1];
    const float* qkv_w  = (const float*)d_in[2];
    const float* proj_w = (const float*)d_in[3];
    const float* proj_b = (const float*)d_in[4];
    float* out = (float*)d_out;

    cudaFuncSetAttribute(qkv_gemm_kernel,
                         cudaFuncAttributeMaxDynamicSharedMemorySize, GEMM_SMEM_BYTES);
    cudaFuncSetAttribute(proj_gemm_kernel,
                         cudaFuncAttributeMaxDynamicSharedMemorySize, GEMM_SMEM_BYTES);
    cudaFuncSetAttribute(attn_kernel,
                         cudaFuncAttributeMaxDynamicSharedMemorySize, ATTN_SMEM_BYTES);

    // 1) QKV projection + scatter to [B,H,N,DH]
    {
        dim3 grid(3 * C_ / 128, (B_ * N_) / 128); // (24, 32)
        qkv_gemm_kernel<<<grid, 256, GEMM_SMEM_BYTES>>>(x, qkv_w);
    }
    // 2) RoPE on q and k
    {
        const int total = B_ * H_ * N_ * 32;
        rope_kernel<<<(total + 255) / 256, 256>>>(pos);
    }
    // 3) Attention
    {
        dim3 grid(N_ / 128, H_, B_); // (16, 16, 2)
        attn_kernel<<<grid, 256, ATTN_SMEM_BYTES>>>();
    }
    // 4) Output projection + bias
    {
        dim3 grid(C_ / 128, (B_ * N_) / 128); // (8, 32)
        proj_gemm_kernel<<<grid, 256, GEMM_SMEM_BYTES>>>(proj_w, proj_b, out);
    }
}